// round 7
// baseline (speedup 1.0000x reference)
#include <cuda_runtime.h>

// Fused autoencoder forward + Jacobians. 2 samples/thread, everything packed
// as f32x2 across the sample pair (natural pairs -> no dup movs). Weights in
// __constant__, pre-duplicated / pre-multiplied / pre-scaled by a prep kernel:
//   - L1 weights & biases scaled by log2e  (z carried in log2 domain)
//   - W3 scaled by ln2 for the value accumulators (absorbs domain conversion)
//   - p0 = W2*W1[:,0], p1 = W2*W1[:,1] premultiplied -> tangent arrays ta/tb
//     replaced by the sigmoid array S alone (halves per-sample array regs)
// Outputs: theta[N,2] | J_h[N,2,2] | q_hat[N,2] | J_h_dec[N,2,2] | J_h_ana[N,2,2]

typedef unsigned long long pf;   // packed (sampleA, sampleB) f32 pair
union PU { pf u; float2 f; };

__device__ __forceinline__ pf pk(float a, float b) { PU c; c.f = make_float2(a, b); return c.u; }
__device__ __forceinline__ pf pkf(float2 v)        { PU c; c.f = v; return c.u; }
__device__ __forceinline__ float2 up(pf u)         { PU c; c.u = u; return c.f; }
__device__ __forceinline__ pf ffma2(pf a, pf b, pf c) {
    pf d; asm("fma.rn.f32x2 %0, %1, %2, %3;" : "=l"(d) : "l"(a), "l"(b), "l"(c)); return d;
}
__device__ __forceinline__ pf fmul2(pf a, pf b) {
    pf d; asm("mul.rn.f32x2 %0, %1, %2;" : "=l"(d) : "l"(a), "l"(b)); return d;
}
__device__ __forceinline__ float ex2f(float x) {
    float r; asm("ex2.approx.ftz.f32 %0, %1;" : "=f"(r) : "f"(x)); return r;
}
__device__ __forceinline__ float lg2f(float x) {
    float r; asm("lg2.approx.ftz.f32 %0, %1;" : "=f"(r) : "f"(x)); return r;
}

struct MLPW {
    float4 a1[16];    // (w10*L2E dup, w11*L2E dup)
    float2 b1d[16];   // dup b1*L2E
    float4 q0[256];   // (w2 dup, p0 dup),  p0 = w2*w1[i][0]
    float2 q1[256];   // (p1 dup),          p1 = w2*w1[i][1]
    float2 b2d[16];   // dup b2*L2E
    float4 w3s[16];   // (w3[0][j]*LN2 dup, w3[1][j]*LN2 dup)
    float4 w3t[16];   // (w3[0][j] dup,     w3[1][j] dup)
    float2 b3d0, b3d1;
};
struct CData { MLPW m[2]; };

__constant__ CData CW;
__device__   CData g_scratch;

// log2-domain softplus pair + sigmoid pair.
// zL = z*log2e;  h' = max(zL,0)+lg2(1+2^-|zL|) = softplus(z)*log2e
// s  = 2^(min(zL,0)-lg2(1+2^-|zL|)) = sigmoid(z)
__device__ __forceinline__ void act1(float zL, float& h, float& s) {
    float t = ex2f(-fabsf(zL));
    float g = lg2f(1.0f + t);
    h = fmaxf(zL, 0.0f) + g;
    s = ex2f(fminf(zL, 0.0f) - g);
}
__device__ __forceinline__ void actp(pf z, pf& H, pf& S) {
    float2 zv = up(z);
    float h0, s0, h1, s1;
    act1(zv.x, h0, s0);
    act1(zv.y, h1, s1);
    H = pk(h0, h1);
    S = pk(s0, s1);
}

// MLP 2->16->16->2 for a sample pair. X0=(x0A,x0B), X1=(x1A,x1B).
// Returns Y0=(y0A,y0B), Y1=(y1A,y1B) and Jacobian entries packed across samples.
template<int E>
__device__ __forceinline__ void mlp(pf X0, pf X1,
                                    pf& Y0, pf& Y1,
                                    pf& J00, pf& J01, pf& J10, pf& J11)
{
    const MLPW& W = CW.m[E];
    pf H[16], S[16];
#pragma unroll
    for (int i = 0; i < 16; ++i) {
        float4 a = W.a1[i];
        pf z = ffma2(pk(a.x, a.y), X0,
                ffma2(pk(a.z, a.w), X1, pkf(W.b1d[i])));
        actp(z, H[i], S[i]);
    }

    Y0 = pkf(W.b3d0);
    Y1 = pkf(W.b3d1);
    J00 = 0; J01 = 0; J10 = 0; J11 = 0;
#pragma unroll
    for (int j = 0; j < 16; ++j) {
        pf z = pkf(W.b2d[j]);
        pf a = 0, b = 0;
#pragma unroll
        for (int i = 0; i < 16; ++i) {
            float4 c0 = W.q0[16 * j + i];
            z = ffma2(pk(c0.x, c0.y), H[i], z);
            a = ffma2(pk(c0.z, c0.w), S[i], a);
            b = ffma2(pkf(W.q1[16 * j + i]), S[i], b);
        }
        pf H2, S2;
        actp(z, H2, S2);
        pf SA = fmul2(S2, a);
        pf SB = fmul2(S2, b);
        float4 ws = W.w3s[j];
        float4 wt = W.w3t[j];
        Y0  = ffma2(pk(ws.x, ws.y), H2, Y0);
        Y1  = ffma2(pk(ws.z, ws.w), H2, Y1);
        J00 = ffma2(pk(wt.x, wt.y), SA, J00);
        J01 = ffma2(pk(wt.x, wt.y), SB, J01);
        J10 = ffma2(pk(wt.z, wt.w), SA, J10);
        J11 = ffma2(pk(wt.z, wt.w), SB, J11);
    }
}

__global__ void __launch_bounds__(256) prep_kernel(
    const float* __restrict__ ew1, const float* __restrict__ eb1,
    const float* __restrict__ ew2, const float* __restrict__ eb2,
    const float* __restrict__ ew3, const float* __restrict__ eb3,
    const float* __restrict__ dw1, const float* __restrict__ db1,
    const float* __restrict__ dw2, const float* __restrict__ db2,
    const float* __restrict__ dw3, const float* __restrict__ db3)
{
    const float L2E = 1.442695041f, LN2 = 0.6931471806f;
    const int t = threadIdx.x;
    const float* W1[2] = {ew1, dw1};
    const float* B1[2] = {eb1, db1};
    const float* W2[2] = {ew2, dw2};
    const float* B2[2] = {eb2, db2};
    const float* W3[2] = {ew3, dw3};
    const float* B3[2] = {eb3, db3};

#pragma unroll
    for (int E = 0; E < 2; ++E) {
        MLPW& M = g_scratch.m[E];
        // q0/q1: 256 entries
        {
            int j = t / 16, i = t % 16;
            float w2 = W2[E][t];
            float p0 = w2 * W1[E][2 * i];
            float p1 = w2 * W1[E][2 * i + 1];
            M.q0[t] = make_float4(w2, w2, p0, p0);
            M.q1[t] = make_float2(p1, p1);
            (void)j;
        }
        if (t < 16) {
            float w10 = W1[E][2 * t] * L2E;
            float w11 = W1[E][2 * t + 1] * L2E;
            M.a1[t]  = make_float4(w10, w10, w11, w11);
            M.b1d[t] = make_float2(B1[E][t] * L2E, B1[E][t] * L2E);
            M.b2d[t] = make_float2(B2[E][t] * L2E, B2[E][t] * L2E);
            float w30 = W3[E][t], w31 = W3[E][16 + t];
            M.w3s[t] = make_float4(w30 * LN2, w30 * LN2, w31 * LN2, w31 * LN2);
            M.w3t[t] = make_float4(w30, w30, w31, w31);
        }
        if (t == 0) {
            M.b3d0 = make_float2(B3[E][0], B3[E][0]);
            M.b3d1 = make_float2(B3[E][1], B3[E][1]);
        }
    }
}

__global__ void __launch_bounds__(128, 4) ae_kernel(
    const float* __restrict__ q, float* __restrict__ out, int N)
{
    const int M = (N + 1) / 2;
    const int n = blockIdx.x * 128 + threadIdx.x;
    if (n >= M) return;
    const bool hasB = (n + M) < N;
    const int iA = n;
    const int iB = hasB ? (n + M) : n;

    const float2 qa = reinterpret_cast<const float2*>(q)[iA];
    const float2 qb = reinterpret_cast<const float2*>(q)[iB];
    pf X0 = pk(qa.x, qb.x);
    pf X1 = pk(qa.y, qb.y);

    pf T0, T1, JH00, JH01, JH10, JH11;
    mlp<0>(X0, X1, T0, T1, JH00, JH01, JH10, JH11);

    pf Q0, Q1, JD00, JD01, JD10, JD11;
    mlp<1>(T0, T1, Q0, Q1, JD00, JD01, JD10, JD11);

    // analytic jacobian per lane
    float ja[2][4];
#pragma unroll
    for (int l = 0; l < 2; ++l) {
        float q0 = l ? qb.x : qa.x;
        float q1 = l ? qb.y : qa.y;
        float r2  = fmaf(q0, q0, q1 * q1);
        float inv = __fdividef(1.0f, r2);
        float isr = rsqrtf(r2 + 1e-8f);
        ja[l][0] = -q1 * inv;
        ja[l][1] =  q0 * inv;
        ja[l][2] =  q0 * isr;
        ja[l][3] =  q1 * isr;
    }

    const size_t Ns = (size_t)N;
    float2* o_theta = reinterpret_cast<float2*>(out);
    float4* o_jh    = reinterpret_cast<float4*>(out + 2 * Ns);
    float2* o_qhat  = reinterpret_cast<float2*>(out + 6 * Ns);
    float4* o_jd    = reinterpret_cast<float4*>(out + 8 * Ns);
    float4* o_ja    = reinterpret_cast<float4*>(out + 12 * Ns);

    float2 t0 = up(T0), t1 = up(T1);
    float2 h00 = up(JH00), h01 = up(JH01), h10 = up(JH10), h11 = up(JH11);
    float2 q0v = up(Q0), q1v = up(Q1);
    float2 d00 = up(JD00), d01 = up(JD01), d10 = up(JD10), d11 = up(JD11);

    o_theta[iA] = make_float2(t0.x, t1.x);
    o_jh[iA]    = make_float4(h00.x, h01.x, h10.x, h11.x);
    o_qhat[iA]  = make_float2(q0v.x, q1v.x);
    o_jd[iA]    = make_float4(d00.x, d01.x, d10.x, d11.x);
    o_ja[iA]    = make_float4(ja[0][0], ja[0][1], ja[0][2], ja[0][3]);

    if (hasB) {
        o_theta[iB] = make_float2(t0.y, t1.y);
        o_jh[iB]    = make_float4(h00.y, h01.y, h10.y, h11.y);
        o_qhat[iB]  = make_float2(q0v.y, q1v.y);
        o_jd[iB]    = make_float4(d00.y, d01.y, d10.y, d11.y);
        o_ja[iB]    = make_float4(ja[1][0], ja[1][1], ja[1][2], ja[1][3]);
    }
}

extern "C" void kernel_launch(void* const* d_in, const int* in_sizes, int n_in,
                              void* d_out, int out_size) {
    const float* q = (const float*)d_in[0];

    prep_kernel<<<1, 256>>>(
        (const float*)d_in[1], (const float*)d_in[2],
        (const float*)d_in[3], (const float*)d_in[4],
        (const float*)d_in[5], (const float*)d_in[6],
        (const float*)d_in[7], (const float*)d_in[8],
        (const float*)d_in[9], (const float*)d_in[10],
        (const float*)d_in[11], (const float*)d_in[12]);

    void* cw_addr = nullptr;
    void* sc_addr = nullptr;
    cudaGetSymbolAddress(&cw_addr, CW);
    cudaGetSymbolAddress(&sc_addr, g_scratch);
    cudaMemcpyAsync(cw_addr, sc_addr, sizeof(CData),
                    cudaMemcpyDeviceToDevice, 0);

    const int N = in_sizes[0] / 2;
    const int M = (N + 1) / 2;
    const int blocks = (M + 127) / 128;
    ae_kernel<<<blocks, 128>>>(q, (float*)d_out, N);
}

// round 8
// speedup vs baseline: 1.0003x; 1.0003x over previous
#include <cuda_runtime.h>

// Fused autoencoder forward + Jacobians. 2 samples/thread, everything packed
// as f32x2 across the sample pair (natural pairs -> no dup movs). Weights in
// __constant__, pre-duplicated / pre-multiplied / pre-scaled by a prep kernel:
//   - L1 weights & biases scaled by log2e  (z carried in log2 domain)
//   - W3 scaled by ln2 for the value accumulators (absorbs domain conversion)
//   - p0 = W2*W1[:,0], p1 = W2*W1[:,1] premultiplied -> tangent arrays ta/tb
//     replaced by the sigmoid array S alone (halves per-sample array regs)
// Outputs: theta[N,2] | J_h[N,2,2] | q_hat[N,2] | J_h_dec[N,2,2] | J_h_ana[N,2,2]

typedef unsigned long long pf;   // packed (sampleA, sampleB) f32 pair
union PU { pf u; float2 f; };

__device__ __forceinline__ pf pk(float a, float b) { PU c; c.f = make_float2(a, b); return c.u; }
__device__ __forceinline__ pf pkf(float2 v)        { PU c; c.f = v; return c.u; }
__device__ __forceinline__ float2 up(pf u)         { PU c; c.u = u; return c.f; }
__device__ __forceinline__ pf ffma2(pf a, pf b, pf c) {
    pf d; asm("fma.rn.f32x2 %0, %1, %2, %3;" : "=l"(d) : "l"(a), "l"(b), "l"(c)); return d;
}
__device__ __forceinline__ pf fmul2(pf a, pf b) {
    pf d; asm("mul.rn.f32x2 %0, %1, %2;" : "=l"(d) : "l"(a), "l"(b)); return d;
}
__device__ __forceinline__ float ex2f(float x) {
    float r; asm("ex2.approx.ftz.f32 %0, %1;" : "=f"(r) : "f"(x)); return r;
}
__device__ __forceinline__ float lg2f(float x) {
    float r; asm("lg2.approx.ftz.f32 %0, %1;" : "=f"(r) : "f"(x)); return r;
}

struct MLPW {
    float4 a1[16];    // (w10*L2E dup, w11*L2E dup)
    float2 b1d[16];   // dup b1*L2E
    float4 q0[256];   // (w2 dup, p0 dup),  p0 = w2*w1[i][0]
    float2 q1[256];   // (p1 dup),          p1 = w2*w1[i][1]
    float2 b2d[16];   // dup b2*L2E
    float4 w3s[16];   // (w3[0][j]*LN2 dup, w3[1][j]*LN2 dup)
    float4 w3t[16];   // (w3[0][j] dup,     w3[1][j] dup)
    float2 b3d0, b3d1;
};
struct CData { MLPW m[2]; };

__constant__ CData CW;
__device__   CData g_scratch;

// log2-domain softplus pair + sigmoid pair.
// zL = z*log2e;  h' = max(zL,0)+lg2(1+2^-|zL|) = softplus(z)*log2e
// s  = 2^(min(zL,0)-lg2(1+2^-|zL|)) = sigmoid(z)
__device__ __forceinline__ void act1(float zL, float& h, float& s) {
    float t = ex2f(-fabsf(zL));
    float g = lg2f(1.0f + t);
    h = fmaxf(zL, 0.0f) + g;
    s = ex2f(fminf(zL, 0.0f) - g);
}
__device__ __forceinline__ void actp(pf z, pf& H, pf& S) {
    float2 zv = up(z);
    float h0, s0, h1, s1;
    act1(zv.x, h0, s0);
    act1(zv.y, h1, s1);
    H = pk(h0, h1);
    S = pk(s0, s1);
}

// MLP 2->16->16->2 for a sample pair. X0=(x0A,x0B), X1=(x1A,x1B).
// Returns Y0=(y0A,y0B), Y1=(y1A,y1B) and Jacobian entries packed across samples.
template<int E>
__device__ __forceinline__ void mlp(pf X0, pf X1,
                                    pf& Y0, pf& Y1,
                                    pf& J00, pf& J01, pf& J10, pf& J11)
{
    const MLPW& W = CW.m[E];
    pf H[16], S[16];
#pragma unroll
    for (int i = 0; i < 16; ++i) {
        float4 a = W.a1[i];
        pf z = ffma2(pk(a.x, a.y), X0,
                ffma2(pk(a.z, a.w), X1, pkf(W.b1d[i])));
        actp(z, H[i], S[i]);
    }

    Y0 = pkf(W.b3d0);
    Y1 = pkf(W.b3d1);
    J00 = 0; J01 = 0; J10 = 0; J11 = 0;
#pragma unroll
    for (int j = 0; j < 16; ++j) {
        pf z = pkf(W.b2d[j]);
        pf a = 0, b = 0;
#pragma unroll
        for (int i = 0; i < 16; ++i) {
            float4 c0 = W.q0[16 * j + i];
            z = ffma2(pk(c0.x, c0.y), H[i], z);
            a = ffma2(pk(c0.z, c0.w), S[i], a);
            b = ffma2(pkf(W.q1[16 * j + i]), S[i], b);
        }
        pf H2, S2;
        actp(z, H2, S2);
        pf SA = fmul2(S2, a);
        pf SB = fmul2(S2, b);
        float4 ws = W.w3s[j];
        float4 wt = W.w3t[j];
        Y0  = ffma2(pk(ws.x, ws.y), H2, Y0);
        Y1  = ffma2(pk(ws.z, ws.w), H2, Y1);
        J00 = ffma2(pk(wt.x, wt.y), SA, J00);
        J01 = ffma2(pk(wt.x, wt.y), SB, J01);
        J10 = ffma2(pk(wt.z, wt.w), SA, J10);
        J11 = ffma2(pk(wt.z, wt.w), SB, J11);
    }
}

__global__ void __launch_bounds__(256) prep_kernel(
    const float* __restrict__ ew1, const float* __restrict__ eb1,
    const float* __restrict__ ew2, const float* __restrict__ eb2,
    const float* __restrict__ ew3, const float* __restrict__ eb3,
    const float* __restrict__ dw1, const float* __restrict__ db1,
    const float* __restrict__ dw2, const float* __restrict__ db2,
    const float* __restrict__ dw3, const float* __restrict__ db3)
{
    const float L2E = 1.442695041f, LN2 = 0.6931471806f;
    const int t = threadIdx.x;
    const float* W1[2] = {ew1, dw1};
    const float* B1[2] = {eb1, db1};
    const float* W2[2] = {ew2, dw2};
    const float* B2[2] = {eb2, db2};
    const float* W3[2] = {ew3, dw3};
    const float* B3[2] = {eb3, db3};

#pragma unroll
    for (int E = 0; E < 2; ++E) {
        MLPW& M = g_scratch.m[E];
        // q0/q1: 256 entries
        {
            int j = t / 16, i = t % 16;
            float w2 = W2[E][t];
            float p0 = w2 * W1[E][2 * i];
            float p1 = w2 * W1[E][2 * i + 1];
            M.q0[t] = make_float4(w2, w2, p0, p0);
            M.q1[t] = make_float2(p1, p1);
            (void)j;
        }
        if (t < 16) {
            float w10 = W1[E][2 * t] * L2E;
            float w11 = W1[E][2 * t + 1] * L2E;
            M.a1[t]  = make_float4(w10, w10, w11, w11);
            M.b1d[t] = make_float2(B1[E][t] * L2E, B1[E][t] * L2E);
            M.b2d[t] = make_float2(B2[E][t] * L2E, B2[E][t] * L2E);
            float w30 = W3[E][t], w31 = W3[E][16 + t];
            M.w3s[t] = make_float4(w30 * LN2, w30 * LN2, w31 * LN2, w31 * LN2);
            M.w3t[t] = make_float4(w30, w30, w31, w31);
        }
        if (t == 0) {
            M.b3d0 = make_float2(B3[E][0], B3[E][0]);
            M.b3d1 = make_float2(B3[E][1], B3[E][1]);
        }
    }
}

__global__ void __launch_bounds__(128, 4) ae_kernel(
    const float* __restrict__ q, float* __restrict__ out, int N)
{
    const int M = (N + 1) / 2;
    const int n = blockIdx.x * 128 + threadIdx.x;
    if (n >= M) return;
    const bool hasB = (n + M) < N;
    const int iA = n;
    const int iB = hasB ? (n + M) : n;

    const float2 qa = reinterpret_cast<const float2*>(q)[iA];
    const float2 qb = reinterpret_cast<const float2*>(q)[iB];
    pf X0 = pk(qa.x, qb.x);
    pf X1 = pk(qa.y, qb.y);

    pf T0, T1, JH00, JH01, JH10, JH11;
    mlp<0>(X0, X1, T0, T1, JH00, JH01, JH10, JH11);

    pf Q0, Q1, JD00, JD01, JD10, JD11;
    mlp<1>(T0, T1, Q0, Q1, JD00, JD01, JD10, JD11);

    // analytic jacobian per lane
    float ja[2][4];
#pragma unroll
    for (int l = 0; l < 2; ++l) {
        float q0 = l ? qb.x : qa.x;
        float q1 = l ? qb.y : qa.y;
        float r2  = fmaf(q0, q0, q1 * q1);
        float inv = __fdividef(1.0f, r2);
        float isr = rsqrtf(r2 + 1e-8f);
        ja[l][0] = -q1 * inv;
        ja[l][1] =  q0 * inv;
        ja[l][2] =  q0 * isr;
        ja[l][3] =  q1 * isr;
    }

    const size_t Ns = (size_t)N;
    float2* o_theta = reinterpret_cast<float2*>(out);
    float4* o_jh    = reinterpret_cast<float4*>(out + 2 * Ns);
    float2* o_qhat  = reinterpret_cast<float2*>(out + 6 * Ns);
    float4* o_jd    = reinterpret_cast<float4*>(out + 8 * Ns);
    float4* o_ja    = reinterpret_cast<float4*>(out + 12 * Ns);

    float2 t0 = up(T0), t1 = up(T1);
    float2 h00 = up(JH00), h01 = up(JH01), h10 = up(JH10), h11 = up(JH11);
    float2 q0v = up(Q0), q1v = up(Q1);
    float2 d00 = up(JD00), d01 = up(JD01), d10 = up(JD10), d11 = up(JD11);

    o_theta[iA] = make_float2(t0.x, t1.x);
    o_jh[iA]    = make_float4(h00.x, h01.x, h10.x, h11.x);
    o_qhat[iA]  = make_float2(q0v.x, q1v.x);
    o_jd[iA]    = make_float4(d00.x, d01.x, d10.x, d11.x);
    o_ja[iA]    = make_float4(ja[0][0], ja[0][1], ja[0][2], ja[0][3]);

    if (hasB) {
        o_theta[iB] = make_float2(t0.y, t1.y);
        o_jh[iB]    = make_float4(h00.y, h01.y, h10.y, h11.y);
        o_qhat[iB]  = make_float2(q0v.y, q1v.y);
        o_jd[iB]    = make_float4(d00.y, d01.y, d10.y, d11.y);
        o_ja[iB]    = make_float4(ja[1][0], ja[1][1], ja[1][2], ja[1][3]);
    }
}

extern "C" void kernel_launch(void* const* d_in, const int* in_sizes, int n_in,
                              void* d_out, int out_size) {
    const float* q = (const float*)d_in[0];

    prep_kernel<<<1, 256>>>(
        (const float*)d_in[1], (const float*)d_in[2],
        (const float*)d_in[3], (const float*)d_in[4],
        (const float*)d_in[5], (const float*)d_in[6],
        (const float*)d_in[7], (const float*)d_in[8],
        (const float*)d_in[9], (const float*)d_in[10],
        (const float*)d_in[11], (const float*)d_in[12]);

    void* cw_addr = nullptr;
    void* sc_addr = nullptr;
    cudaGetSymbolAddress(&cw_addr, CW);
    cudaGetSymbolAddress(&sc_addr, g_scratch);
    cudaMemcpyAsync(cw_addr, sc_addr, sizeof(CData),
                    cudaMemcpyDeviceToDevice, 0);

    const int N = in_sizes[0] / 2;
    const int M = (N + 1) / 2;
    const int blocks = (M + 127) / 128;
    ae_kernel<<<blocks, 128>>>(q, (float*)d_out, N);
}

// round 10
// speedup vs baseline: 1.0394x; 1.0390x over previous
#include <cuda_runtime.h>
#include <cuda_bf16.h>
#include <cstdint>

// Fused autoencoder fwd + Jacobians via warp-level mma.sync (bf16 split, f32 acc).
// Per warp-tile of 32 samples, per MLP: Z = H*Bz (N=16), AB = S*Babs (N=32).
// Outputs: theta[N,2] | J_h[N,2,2] | q_hat[N,2] | J_h_dec[N,2,2] | J_h_ana[N,2,2]

#define STG_STRIDE 144
#define SM_STG   0                        // 4 warps * 32 rows * 144 = 18432
#define SM_ZB    (4 * 32 * STG_STRIDE)    // 4 matrices * 16 rows * 48 = 3072
#define SM_ABB   (SM_ZB + 4 * 16 * 48)    // 4 matrices * 16 rows * 80 = 5120
#define SM_SWF   (SM_ABB + 4 * 16 * 80)   // 2 * 100 floats
#define SM_TOT   (SM_SWF + 800)

__device__ __forceinline__ uint32_t s2u(const void* p) {
    uint32_t a;
    asm("{.reg .u64 t; cvta.to.shared.u64 t,%1; cvt.u32.u64 %0,t;}" : "=r"(a) : "l"(p));
    return a;
}
__device__ __forceinline__ void ldsm4(uint32_t& r0, uint32_t& r1, uint32_t& r2, uint32_t& r3, uint32_t a) {
    asm volatile("ldmatrix.sync.aligned.m8n8.x4.shared.b16 {%0,%1,%2,%3},[%4];"
                 : "=r"(r0), "=r"(r1), "=r"(r2), "=r"(r3) : "r"(a));
}
__device__ __forceinline__ void ldsm4t(uint32_t& r0, uint32_t& r1, uint32_t& r2, uint32_t& r3, uint32_t a) {
    asm volatile("ldmatrix.sync.aligned.m8n8.x4.trans.shared.b16 {%0,%1,%2,%3},[%4];"
                 : "=r"(r0), "=r"(r1), "=r"(r2), "=r"(r3) : "r"(a));
}
__device__ __forceinline__ void mma16816(float* d, uint32_t a0, uint32_t a1, uint32_t a2, uint32_t a3,
                                         uint32_t b0, uint32_t b1) {
    asm volatile("mma.sync.aligned.m16n8k16.row.col.f32.bf16.bf16.f32 "
                 "{%0,%1,%2,%3},{%4,%5,%6,%7},{%8,%9},{%0,%1,%2,%3};"
                 : "+f"(d[0]), "+f"(d[1]), "+f"(d[2]), "+f"(d[3])
                 : "r"(a0), "r"(a1), "r"(a2), "r"(a3), "r"(b0), "r"(b1));
}

__device__ __forceinline__ void act(float z, float& h, float& s) {
    const float L2E = 1.442695041f, LN2 = 0.6931471806f;
    float t, g;
    asm("ex2.approx.ftz.f32 %0,%1;" : "=f"(t) : "f"(fabsf(z) * -L2E));
    asm("lg2.approx.ftz.f32 %0,%1;" : "=f"(g) : "f"(1.0f + t));
    h = fmaf(g, LN2, fmaxf(z, 0.0f));
    asm("ex2.approx.ftz.f32 %0,%1;" : "=f"(s) : "f"(fmaf(fminf(z, 0.0f), L2E, -g)));
}
__device__ __forceinline__ float trhi(float v) { return __uint_as_float(__float_as_uint(v) & 0xffff0000u); }
__device__ __forceinline__ uint32_t bfp(float a, float b) {  // a -> low half
    uint32_t r;
    asm("cvt.rn.bf16x2.f32 %0,%1,%2;" : "=r"(r) : "f"(b), "f"(a));
    return r;
}

struct Ctx {
    char*    rowPtr;   // staging row own_row (this warp)
    uint32_t aBase;    // lane addr for A ldmatrix, rb=0, matOff=0
    uint32_t zBase;    // lane addr in ZB (E=0, hi)
    uint32_t abBase;   // lane addr in ABB (E=0, hi)
    const float* swf;
    int m;
};

// One MLP: x -> (y0,y1,J00,J01,J10,J11) for this lane's own row. res[6].
__device__ void phase(const Ctx& c, int E, float x0, float x1, float res[6]) {
    const float* o = c.swf + E * 100;

    // layer 1 (scalar, own row)
    float hv[16], sv[16];
#pragma unroll
    for (int i = 0; i < 16; ++i) {
        float z = fmaf(o[2 * i], x0, fmaf(o[2 * i + 1], x1, o[32 + i]));
        act(z, hv[i], sv[i]);
    }
    // split hi/lo, pack bf16x2
    uint32_t ph[8], pl[8], qh[8], ql[8];
#pragma unroll
    for (int k = 0; k < 8; ++k) {
        float a = hv[2 * k], b = hv[2 * k + 1];
        float ah = trhi(a), bh = trhi(b);
        ph[k] = bfp(ah, bh);  pl[k] = bfp(a - ah, b - bh);
        a = sv[2 * k]; b = sv[2 * k + 1];
        ah = trhi(a); bh = trhi(b);
        qh[k] = bfp(ah, bh);  ql[k] = bfp(a - ah, b - bh);
    }
    __syncwarp();   // protect prior ldmatrix consumers before overwrite
    uint4* rw = (uint4*)c.rowPtr;   // row: [Hhi32|Hlo32|Shi32|Slo32|pad16]
    rw[0] = make_uint4(ph[0], ph[1], ph[2], ph[3]);
    rw[1] = make_uint4(ph[4], ph[5], ph[6], ph[7]);
    rw[2] = make_uint4(pl[0], pl[1], pl[2], pl[3]);
    rw[3] = make_uint4(pl[4], pl[5], pl[6], pl[7]);
    rw[4] = make_uint4(qh[0], qh[1], qh[2], qh[3]);
    rw[5] = make_uint4(qh[4], qh[5], qh[6], qh[7]);
    rw[6] = make_uint4(ql[0], ql[1], ql[2], ql[3]);
    rw[7] = make_uint4(ql[4], ql[5], ql[6], ql[7]);
    __syncwarp();

    // A fragments
    uint32_t Hh[2][4], Hl[2][4], Sh[2][4], Sl[2][4];
#pragma unroll
    for (int rb = 0; rb < 2; ++rb) {
        uint32_t ba = c.aBase + rb * (16 * STG_STRIDE);
        ldsm4(Hh[rb][0], Hh[rb][1], Hh[rb][2], Hh[rb][3], ba + 0);
        ldsm4(Hl[rb][0], Hl[rb][1], Hl[rb][2], Hl[rb][3], ba + 32);
        ldsm4(Sh[rb][0], Sh[rb][1], Sh[rb][2], Sh[rb][3], ba + 64);
        ldsm4(Sl[rb][0], Sl[rb][1], Sl[rb][2], Sl[rb][3], ba + 96);
    }
    // B fragments (trans loads of K-major tiles)
    uint32_t zh[4], zl[4], abh[8], abl[8];
    uint32_t za = c.zBase + E * 1536;
    ldsm4t(zh[0], zh[1], zh[2], zh[3], za);
    ldsm4t(zl[0], zl[1], zl[2], zl[3], za + 768);
    uint32_t aa = c.abBase + E * 2560;
    ldsm4t(abh[0], abh[1], abh[2], abh[3], aa);
    ldsm4t(abh[4], abh[5], abh[6], abh[7], aa + 32);
    ldsm4t(abl[0], abl[1], abl[2], abl[3], aa + 1280);
    ldsm4t(abl[4], abl[5], abl[6], abl[7], aa + 1280 + 32);

    float Zc[2][2][4] = {};
    float Ac[2][4][4] = {};
#pragma unroll
    for (int rb = 0; rb < 2; ++rb) {
        mma16816(Zc[rb][0], Hh[rb][0], Hh[rb][1], Hh[rb][2], Hh[rb][3], zh[0], zh[1]);
        mma16816(Zc[rb][1], Hh[rb][0], Hh[rb][1], Hh[rb][2], Hh[rb][3], zh[2], zh[3]);
        mma16816(Zc[rb][0], Hh[rb][0], Hh[rb][1], Hh[rb][2], Hh[rb][3], zl[0], zl[1]);
        mma16816(Zc[rb][1], Hh[rb][0], Hh[rb][1], Hh[rb][2], Hh[rb][3], zl[2], zl[3]);
        mma16816(Zc[rb][0], Hl[rb][0], Hl[rb][1], Hl[rb][2], Hl[rb][3], zh[0], zh[1]);
        mma16816(Zc[rb][1], Hl[rb][0], Hl[rb][1], Hl[rb][2], Hl[rb][3], zh[2], zh[3]);
#pragma unroll
        for (int cb = 0; cb < 4; ++cb) {
            mma16816(Ac[rb][cb], Sh[rb][0], Sh[rb][1], Sh[rb][2], Sh[rb][3], abh[2 * cb], abh[2 * cb + 1]);
            mma16816(Ac[rb][cb], Sh[rb][0], Sh[rb][1], Sh[rb][2], Sh[rb][3], abl[2 * cb], abl[2 * cb + 1]);
            mma16816(Ac[rb][cb], Sl[rb][0], Sl[rb][1], Sl[rb][2], Sl[rb][3], abh[2 * cb], abh[2 * cb + 1]);
        }
    }

    // epilogue in fragment layout; thread lane holds j = m + 4*jj
    float b2v[4], w0v[4], w1v[4];
#pragma unroll
    for (int jj = 0; jj < 4; ++jj) {
        int j = c.m + 4 * jj;
        b2v[jj] = o[48 + j];
        w0v[jj] = o[64 + j];
        w1v[jj] = o[80 + j];
    }
#pragma unroll
    for (int s = 0; s < 4; ++s) {           // slot (rb,u); lane m==s keeps
        int rb = s >> 1, u = s & 1;
        float y0 = 0.f, y1 = 0.f, j00 = 0.f, j01 = 0.f, j10 = 0.f, j11 = 0.f;
#pragma unroll
        for (int jj = 0; jj < 4; ++jj) {
            float z = Zc[rb][jj & 1][2 * u + (jj >> 1)] + b2v[jj];
            float h2, s2;
            act(z, h2, s2);
            float av = Ac[rb][jj][2 * u];
            float bv = Ac[rb][jj][2 * u + 1];
            float sa = s2 * av, sb = s2 * bv;
            y0 = fmaf(w0v[jj], h2, y0);  y1 = fmaf(w1v[jj], h2, y1);
            j00 = fmaf(w0v[jj], sa, j00); j01 = fmaf(w0v[jj], sb, j01);
            j10 = fmaf(w1v[jj], sa, j10); j11 = fmaf(w1v[jj], sb, j11);
        }
        y0 += __shfl_xor_sync(~0u, y0, 1);  y0 += __shfl_xor_sync(~0u, y0, 2);
        y1 += __shfl_xor_sync(~0u, y1, 1);  y1 += __shfl_xor_sync(~0u, y1, 2);
        j00 += __shfl_xor_sync(~0u, j00, 1); j00 += __shfl_xor_sync(~0u, j00, 2);
        j01 += __shfl_xor_sync(~0u, j01, 1); j01 += __shfl_xor_sync(~0u, j01, 2);
        j10 += __shfl_xor_sync(~0u, j10, 1); j10 += __shfl_xor_sync(~0u, j10, 2);
        j11 += __shfl_xor_sync(~0u, j11, 1); j11 += __shfl_xor_sync(~0u, j11, 2);
        if (c.m == s) {
            res[0] = y0 + o[96]; res[1] = y1 + o[97];
            res[2] = j00; res[3] = j01; res[4] = j10; res[5] = j11;
        }
    }
}

__global__ void __launch_bounds__(128, 3) ae_mma_kernel(
    const float* __restrict__ q,
    const float* __restrict__ ew1, const float* __restrict__ eb1,
    const float* __restrict__ ew2, const float* __restrict__ eb2,
    const float* __restrict__ ew3, const float* __restrict__ eb3,
    const float* __restrict__ dw1, const float* __restrict__ db1,
    const float* __restrict__ dw2, const float* __restrict__ db2,
    const float* __restrict__ dw3, const float* __restrict__ db3,
    float* __restrict__ out, int N)
{
    __shared__ __align__(16) char sm[SM_TOT];
    const int t = threadIdx.x;
    const float* W1g[2] = {ew1, dw1};
    const float* W2g[2] = {ew2, dw2};

    // Bz: col permutation jmap(col)=((col&7)>>1)+((col>>3)<<2)+((col&1)<<3)
    for (int idx = t; idx < 512; idx += 128) {
        int E = idx >> 8, r = idx & 255, k = r >> 4, col = r & 15;
        int j = ((col & 7) >> 1) + ((col >> 3) << 2) + ((col & 1) << 3);
        float wv = W2g[E][j * 16 + k];
        float hi = trhi(wv), lo = wv - hi;
        char* bz = sm + SM_ZB + E * 1536;
        *(__nv_bfloat16*)(bz + k * 48 + col * 2)       = __float2bfloat16(hi);
        *(__nv_bfloat16*)(bz + 768 + k * 48 + col * 2) = __float2bfloat16(lo);
    }
    // Babs: col=2j -> W2[j][k]*W1[k][0], col=2j+1 -> *W1[k][1]
    for (int idx = t; idx < 1024; idx += 128) {
        int E = idx >> 9, r = idx & 511, k = r >> 5, col = r & 31;
        int j = col >> 1, v = col & 1;
        float wv = W2g[E][j * 16 + k] * W1g[E][2 * k + v];
        float hi = trhi(wv), lo = wv - hi;
        char* bb = sm + SM_ABB + E * 2560;
        *(__nv_bfloat16*)(bb + k * 80 + col * 2)        = __float2bfloat16(hi);
        *(__nv_bfloat16*)(bb + 1280 + k * 80 + col * 2) = __float2bfloat16(lo);
    }
    {
        const float* B1g[2] = {eb1, db1};
        const float* B2g[2] = {eb2, db2};
        const float* W3g[2] = {ew3, dw3};
        const float* B3g[2] = {eb3, db3};
        float* swf = (float*)(sm + SM_SWF);
        if (t < 32) {
            int E = t >> 4, j = t & 15;
            float* o = swf + E * 100;
            o[2 * j] = W1g[E][2 * j];  o[2 * j + 1] = W1g[E][2 * j + 1];
            o[32 + j] = B1g[E][j];     o[48 + j] = B2g[E][j];
            o[64 + j] = W3g[E][j];     o[80 + j] = W3g[E][16 + j];
            if (j < 2) o[96 + j] = B3g[E][j];
        }
    }
    __syncthreads();

    const int l = t & 31, w = t >> 5;
    const int m = l & 3, g = l >> 2;
    const int own = 8 * m + g;
    const int ti = l >> 3, ri = l & 7;
    char* stgW = sm + SM_STG + w * 32 * STG_STRIDE;

    Ctx c;
    c.rowPtr = stgW + own * STG_STRIDE;
    c.aBase  = s2u(stgW) + (8 * (ti & 1) + ri) * STG_STRIDE + (ti >> 1) * 16;
    c.zBase  = s2u(sm + SM_ZB)  + (8 * (ti & 1) + ri) * 48 + (ti >> 1) * 16;
    c.abBase = s2u(sm + SM_ABB) + (8 * (ti & 1) + ri) * 80 + (ti >> 1) * 16;
    c.swf = (const float*)(sm + SM_SWF);
    c.m = m;

    const size_t Ns = (size_t)N;
#pragma unroll
    for (int tile = 0; tile < 2; ++tile) {
        const int n = blockIdx.x * 256 + w * 64 + tile * 32 + own;
        float2 qv = make_float2(0.f, 0.f);
        if (n < N) qv = reinterpret_cast<const float2*>(q)[n];

        float enc[6], dec[6];
        phase(c, 0, qv.x, qv.y, enc);
        phase(c, 1, enc[0], enc[1], dec);

        if (n < N) {
            float q0 = qv.x, q1 = qv.y;
            float r2  = fmaf(q0, q0, q1 * q1);
            float inv = __fdividef(1.0f, r2);
            float isr = rsqrtf(r2 + 1e-8f);
            reinterpret_cast<float2*>(out)[n]          = make_float2(enc[0], enc[1]);
            reinterpret_cast<float4*>(out + 2 * Ns)[n] = make_float4(enc[2], enc[3], enc[4], enc[5]);
            reinterpret_cast<float2*>(out + 6 * Ns)[n] = make_float2(dec[0], dec[1]);
            reinterpret_cast<float4*>(out + 8 * Ns)[n] = make_float4(dec[2], dec[3], dec[4], dec[5]);
            reinterpret_cast<float4*>(out + 12 * Ns)[n] = make_float4(-q1 * inv, q0 * inv, q0 * isr, q1 * isr);
        }
    }
}

extern "C" void kernel_launch(void* const* d_in, const int* in_sizes, int n_in,
                              void* d_out, int out_size) {
    const int N = in_sizes[0] / 2;
    const int blocks = (N + 255) / 256;
    ae_mma_kernel<<<blocks, 128>>>(
        (const float*)d_in[0],
        (const float*)d_in[1], (const float*)d_in[2],
        (const float*)d_in[3], (const float*)d_in[4],
        (const float*)d_in[5], (const float*)d_in[6],
        (const float*)d_in[7], (const float*)d_in[8],
        (const float*)d_in[9], (const float*)d_in[10],
        (const float*)d_in[11], (const float*)d_in[12],
        (float*)d_out, N);
}